// round 1
// baseline (speedup 1.0000x reference)
#include <cuda_runtime.h>
#include <cstdint>
#include <cstddef>

#define N_NODES 50000
#define K_EIG   512
#define F_DIM   128
#define CH      1024
#define NC      49      // ceil(50000/1024)

// Scratch (allocation-free rule: __device__ globals)
__device__ float g_partial[(size_t)NC * K_EIG * F_DIM];   // 12.8 MB
__device__ float g_y[K_EIG * F_DIM];                       // 256 KB

// Split fp32 into hi/lo tf32 parts (3xTF32 trick). hi+lo reproduces a to ~2^-24.
__device__ __forceinline__ void split_tf32(float v, unsigned &hi, unsigned &lo) {
    unsigned h;
    asm("cvt.rna.tf32.f32 %0, %1;" : "=r"(h) : "f"(v));
    float r = v - __uint_as_float(h);
    unsigned l;
    asm("cvt.rna.tf32.f32 %0, %1;" : "=r"(l) : "f"(r));
    hi = h; lo = l;
}

__device__ __forceinline__ void mma8(float* c,
                                     unsigned a0, unsigned a1, unsigned a2, unsigned a3,
                                     unsigned b0, unsigned b1) {
    asm volatile(
        "mma.sync.aligned.m16n8k8.row.col.f32.tf32.tf32.f32 "
        "{%0,%1,%2,%3}, {%4,%5,%6,%7}, {%8,%9}, {%0,%1,%2,%3};"
        : "+f"(c[0]), "+f"(c[1]), "+f"(c[2]), "+f"(c[3])
        : "r"(a0), "r"(a1), "r"(a2), "r"(a3), "r"(b0), "r"(b1));
}

// ---------------------------------------------------------------------------
// Phase 1: partial[ch][k][f] = sum_{n in chunk} U[n,k] * x[n,f]
// Grid: (4 k-tiles, NC n-chunks). CTA tile: 128(k) x 128(f). 256 threads.
// ---------------------------------------------------------------------------
__global__ void __launch_bounds__(256, 1)
phase1_kernel(const float* __restrict__ U, const float* __restrict__ x) {
    __shared__ float sU[32][136];   // [n][k] pad 8 -> conflict-free frag reads
    __shared__ float sX[32][136];   // [n][f]

    const int kt   = blockIdx.x;          // 0..3
    const int ch   = blockIdx.y;          // 0..NC-1
    const int tid  = threadIdx.x;
    const int lane = tid & 31;
    const int wid  = tid >> 5;
    const int wm   = wid >> 2;            // 0..1 (k-halves of 64)
    const int wf   = wid & 3;             // 0..3 (f-quarters of 32)
    const int qr   = lane >> 2;           // 0..7
    const int qc   = lane & 3;            // 0..3

    float acc[4][4][4];
    #pragma unroll
    for (int a = 0; a < 4; a++)
        #pragma unroll
        for (int b = 0; b < 4; b++)
            #pragma unroll
            for (int c = 0; c < 4; c++) acc[a][b][c] = 0.f;

    const int n0 = ch * CH;

    for (int s = 0; s < CH; s += 32) {
        #pragma unroll
        for (int i = 0; i < 4; i++) {
            int idx = tid + i * 256;            // 0..1023
            int row = idx >> 5;                 // 0..31 (n within stage)
            int c4  = (idx & 31) << 2;          // 0..124 float col
            int n   = n0 + s + row;
            float4 vu = make_float4(0.f, 0.f, 0.f, 0.f);
            float4 vx = make_float4(0.f, 0.f, 0.f, 0.f);
            if (n < N_NODES) {
                vu = *(const float4*)(U + (size_t)n * K_EIG + kt * 128 + c4);
                vx = *(const float4*)(x + (size_t)n * F_DIM + c4);
            }
            *(float4*)(&sU[row][c4]) = vu;
            *(float4*)(&sX[row][c4]) = vx;
        }
        __syncthreads();

        #pragma unroll
        for (int r0 = 0; r0 < 32; r0 += 8) {
            unsigned ah[4][4], al[4][4], bh[4][2], bl[4][2];
            #pragma unroll
            for (int mt = 0; mt < 4; mt++) {
                int m = wm * 64 + mt * 16 + qr;            // A row = k
                split_tf32(sU[r0 + qc][m],         ah[mt][0], al[mt][0]);
                split_tf32(sU[r0 + qc][m + 8],     ah[mt][1], al[mt][1]);
                split_tf32(sU[r0 + 4 + qc][m],     ah[mt][2], al[mt][2]);
                split_tf32(sU[r0 + 4 + qc][m + 8], ah[mt][3], al[mt][3]);
            }
            #pragma unroll
            for (int nt = 0; nt < 4; nt++) {
                int f = wf * 32 + nt * 8 + qr;             // B col = f
                split_tf32(sX[r0 + qc][f],     bh[nt][0], bl[nt][0]);
                split_tf32(sX[r0 + 4 + qc][f], bh[nt][1], bl[nt][1]);
            }
            #pragma unroll
            for (int mt = 0; mt < 4; mt++)
                #pragma unroll
                for (int nt = 0; nt < 4; nt++) {
                    mma8(acc[mt][nt], al[mt][0], al[mt][1], al[mt][2], al[mt][3],
                         bh[nt][0], bh[nt][1]);
                    mma8(acc[mt][nt], ah[mt][0], ah[mt][1], ah[mt][2], ah[mt][3],
                         bl[nt][0], bl[nt][1]);
                    mma8(acc[mt][nt], ah[mt][0], ah[mt][1], ah[mt][2], ah[mt][3],
                         bh[nt][0], bh[nt][1]);
                }
        }
        __syncthreads();
    }

    float* pbase = g_partial + (size_t)ch * (K_EIG * F_DIM);
    #pragma unroll
    for (int mt = 0; mt < 4; mt++) {
        int m = wm * 64 + mt * 16 + qr;
        #pragma unroll
        for (int nt = 0; nt < 4; nt++) {
            int f  = wf * 32 + nt * 8 + 2 * qc;
            int kq = kt * 128 + m;
            *(float2*)(pbase + (size_t)kq * F_DIM + f) =
                make_float2(acc[mt][nt][0], acc[mt][nt][1]);
            *(float2*)(pbase + (size_t)(kq + 8) * F_DIM + f) =
                make_float2(acc[mt][nt][2], acc[mt][nt][3]);
        }
    }
}

// ---------------------------------------------------------------------------
// Phase 1.5: y[k][f] = g[k] * sum_ch partial[ch][k][f]   (deterministic order)
// ---------------------------------------------------------------------------
__global__ void phase15_kernel(const float* __restrict__ g) {
    int idx = blockIdx.x * blockDim.x + threadIdx.x;   // 0..65535
    float s = 0.f;
    #pragma unroll 7
    for (int c = 0; c < NC; c++)
        s += g_partial[(size_t)c * (K_EIG * F_DIM) + idx];
    g_y[idx] = s * __ldg(&g[idx >> 7]);
}

// ---------------------------------------------------------------------------
// Phase 2: out[n][f] = relu( sum_k U[n,k] * y[k,f] )
// Grid: 391 CTAs of 128 rows. CTA tile: 128(n) x 128(f). 256 threads.
// ---------------------------------------------------------------------------
__global__ void __launch_bounds__(256, 1)
phase2_kernel(const float* __restrict__ U, float* __restrict__ out) {
    __shared__ float sU[128][36];   // [n][k] pad 4 -> conflict-free A reads
    __shared__ float sY[32][136];   // [k][f] pad 8 -> conflict-free B reads

    const int nb   = blockIdx.x * 128;
    const int tid  = threadIdx.x;
    const int lane = tid & 31;
    const int wid  = tid >> 5;
    const int wm   = wid >> 2;            // 0..1 (n-halves of 64)
    const int wf   = wid & 3;             // 0..3 (f-quarters of 32)
    const int qr   = lane >> 2;
    const int qc   = lane & 3;

    float acc[4][4][4];
    #pragma unroll
    for (int a = 0; a < 4; a++)
        #pragma unroll
        for (int b = 0; b < 4; b++)
            #pragma unroll
            for (int c = 0; c < 4; c++) acc[a][b][c] = 0.f;

    for (int kk = 0; kk < K_EIG; kk += 32) {
        // U tile: 128 rows x 32 k-cols
        #pragma unroll
        for (int i = 0; i < 4; i++) {
            int idx = tid + i * 256;            // 0..1023
            int row = idx >> 3;                 // 0..127
            int c4  = (idx & 7) << 2;           // 0..28
            int n   = nb + row;
            float4 v = make_float4(0.f, 0.f, 0.f, 0.f);
            if (n < N_NODES)
                v = *(const float4*)(U + (size_t)n * K_EIG + kk + c4);
            *(float4*)(&sU[row][c4]) = v;
        }
        // y tile: 32 k-rows x 128 f
        #pragma unroll
        for (int i = 0; i < 4; i++) {
            int idx = tid + i * 256;
            int row = idx >> 5;                 // 0..31
            int c4  = (idx & 31) << 2;
            *(float4*)(&sY[row][c4]) =
                *(const float4*)(g_y + (size_t)(kk + row) * F_DIM + c4);
        }
        __syncthreads();

        #pragma unroll
        for (int r0 = 0; r0 < 32; r0 += 8) {
            unsigned ah[4][4], al[4][4], bh[4][2], bl[4][2];
            #pragma unroll
            for (int mt = 0; mt < 4; mt++) {
                int m = wm * 64 + mt * 16 + qr;            // A row = n
                split_tf32(sU[m][r0 + qc],         ah[mt][0], al[mt][0]);
                split_tf32(sU[m + 8][r0 + qc],     ah[mt][1], al[mt][1]);
                split_tf32(sU[m][r0 + 4 + qc],     ah[mt][2], al[mt][2]);
                split_tf32(sU[m + 8][r0 + 4 + qc], ah[mt][3], al[mt][3]);
            }
            #pragma unroll
            for (int nt = 0; nt < 4; nt++) {
                int f = wf * 32 + nt * 8 + qr;
                split_tf32(sY[r0 + qc][f],     bh[nt][0], bl[nt][0]);
                split_tf32(sY[r0 + 4 + qc][f], bh[nt][1], bl[nt][1]);
            }
            #pragma unroll
            for (int mt = 0; mt < 4; mt++)
                #pragma unroll
                for (int nt = 0; nt < 4; nt++) {
                    mma8(acc[mt][nt], al[mt][0], al[mt][1], al[mt][2], al[mt][3],
                         bh[nt][0], bh[nt][1]);
                    mma8(acc[mt][nt], ah[mt][0], ah[mt][1], ah[mt][2], ah[mt][3],
                         bl[nt][0], bl[nt][1]);
                    mma8(acc[mt][nt], ah[mt][0], ah[mt][1], ah[mt][2], ah[mt][3],
                         bh[nt][0], bh[nt][1]);
                }
        }
        __syncthreads();
    }

    // Epilogue: ReLU + store
    #pragma unroll
    for (int mt = 0; mt < 4; mt++) {
        int n = nb + wm * 64 + mt * 16 + qr;
        #pragma unroll
        for (int nt = 0; nt < 4; nt++) {
            int f = wf * 32 + nt * 8 + 2 * qc;
            if (n < N_NODES) {
                *(float2*)(out + (size_t)n * F_DIM + f) =
                    make_float2(fmaxf(acc[mt][nt][0], 0.f),
                                fmaxf(acc[mt][nt][1], 0.f));
            }
            if (n + 8 < N_NODES) {
                *(float2*)(out + (size_t)(n + 8) * F_DIM + f) =
                    make_float2(fmaxf(acc[mt][nt][2], 0.f),
                                fmaxf(acc[mt][nt][3], 0.f));
            }
        }
    }
}

// ---------------------------------------------------------------------------
extern "C" void kernel_launch(void* const* d_in, const int* in_sizes, int n_in,
                              void* d_out, int out_size) {
    const float* U = nullptr;
    const float* g = nullptr;
    const float* x = nullptr;
    for (int i = 0; i < n_in; i++) {
        if (in_sizes[i] == N_NODES * K_EIG)      U = (const float*)d_in[i];
        else if (in_sizes[i] == K_EIG)           g = (const float*)d_in[i];
        else if (in_sizes[i] == N_NODES * F_DIM) x = (const float*)d_in[i];
    }
    float* out = (float*)d_out;

    phase1_kernel<<<dim3(4, NC), 256>>>(U, x);
    phase15_kernel<<<(K_EIG * F_DIM) / 256, 256>>>(g);
    phase2_kernel<<<(N_NODES + 127) / 128, 256>>>(U, out);
}

// round 2
// speedup vs baseline: 1.5566x; 1.5566x over previous
#include <cuda_runtime.h>
#include <cstdint>
#include <cstddef>

#define N_NODES 50000
#define K_EIG   512
#define F_DIM   128
#define CH      1376      // 43 stages of 32 rows
#define NC      37        // 4 x 37 = 148 CTAs = one full wave
#define NST1    43

#define STR1    136       // smem row stride (136 mod 32 = 8 -> conflict-free frags)
#define ASZ1    (32 * STR1)          // 4352 u32 per 32x128 plane
#define STG1    (4 * ASZ1)           // UH,UL,XH,XL per stage
#define P1_SMEM (2 * STG1 * 4)       // 139264 B

#define STRU2   36        // phase2 U plane stride (36 mod 32 = 4 -> conflict-free)
#define USZ2    (128 * STRU2)        // 4608
#define YSZ2    (32 * STR1)          // 4352
#define STG2    (2 * USZ2 + 2 * YSZ2)
#define P2_SMEM (2 * STG2 * 4)       // 143360 B

// Scratch (__device__ globals per allocation-free rule)
__device__ float    g_partial[(size_t)NC * K_EIG * F_DIM];   // 9.7 MB
__device__ unsigned g_yhi[K_EIG * F_DIM];
__device__ unsigned g_ylo[K_EIG * F_DIM];

__device__ __forceinline__ void split_tf32(float v, unsigned &hi, unsigned &lo) {
    unsigned h;
    asm("cvt.rna.tf32.f32 %0, %1;" : "=r"(h) : "f"(v));
    float r = v - __uint_as_float(h);
    unsigned l;
    asm("cvt.rna.tf32.f32 %0, %1;" : "=r"(l) : "f"(r));
    hi = h; lo = l;
}

__device__ __forceinline__ void split4(float4 v, uint4 &h, uint4 &l) {
    split_tf32(v.x, h.x, l.x);
    split_tf32(v.y, h.y, l.y);
    split_tf32(v.z, h.z, l.z);
    split_tf32(v.w, h.w, l.w);
}

__device__ __forceinline__ void mma8(float* c,
                                     unsigned a0, unsigned a1, unsigned a2, unsigned a3,
                                     unsigned b0, unsigned b1) {
    asm volatile(
        "mma.sync.aligned.m16n8k8.row.col.f32.tf32.tf32.f32 "
        "{%0,%1,%2,%3}, {%4,%5,%6,%7}, {%8,%9}, {%0,%1,%2,%3};"
        : "+f"(c[0]), "+f"(c[1]), "+f"(c[2]), "+f"(c[3])
        : "r"(a0), "r"(a1), "r"(a2), "r"(a3), "r"(b0), "r"(b1));
}

// ---------------------------------------------------------------------------
// Phase 1: partial[ch][k][f] = sum_{n in chunk} U[n,k] * x[n,f]
// Grid (4 k-tiles, 37 chunks) = 148 CTAs. CTA tile 128(k) x 128(f).
// Pre-split tf32 hi/lo stored in smem; double-buffered; 1 barrier/stage.
// ---------------------------------------------------------------------------
__global__ void __launch_bounds__(256)
phase1_kernel(const float* __restrict__ U, const float* __restrict__ x) {
    extern __shared__ unsigned sm[];

    const int kt   = blockIdx.x;
    const int ch   = blockIdx.y;
    const int tid  = threadIdx.x;
    const int lane = tid & 31;
    const int wid  = tid >> 5;
    const int wm   = wid >> 2;            // 0..1
    const int wf   = wid & 3;             // 0..3
    const int qr   = lane >> 2;           // 0..7
    const int qc   = lane & 3;            // 0..3
    const int n0   = ch * CH;

    // loader coords for 4 float4 per matrix
    int lrow[4], lcol[4];
    #pragma unroll
    for (int i = 0; i < 4; i++) {
        int e = tid + i * 256;
        lrow[i] = e >> 5;
        lcol[i] = (e & 31) << 2;
    }

    float acc[4][4][4];
    #pragma unroll
    for (int a = 0; a < 4; a++)
        #pragma unroll
        for (int b = 0; b < 4; b++)
            #pragma unroll
            for (int c = 0; c < 4; c++) acc[a][b][c] = 0.f;

    float4 rU[4], rX[4];

    // prologue: stage 0 -> regs
    #pragma unroll
    for (int i = 0; i < 4; i++) {
        int n = n0 + lrow[i];
        if (n < N_NODES) {
            rU[i] = *(const float4*)(U + (size_t)n * K_EIG + kt * 128 + lcol[i]);
            rX[i] = *(const float4*)(x + (size_t)n * F_DIM + lcol[i]);
        } else {
            rU[i] = make_float4(0.f, 0.f, 0.f, 0.f);
            rX[i] = rU[i];
        }
    }

    for (int s = 0; s < NST1; s++) {
        unsigned* base = sm + (s & 1) * STG1;
        unsigned* UH = base;
        unsigned* UL = base + ASZ1;
        unsigned* XH = base + 2 * ASZ1;
        unsigned* XL = base + 3 * ASZ1;

        // split regs -> smem
        #pragma unroll
        for (int i = 0; i < 4; i++) {
            uint4 h, l;
            int off = lrow[i] * STR1 + lcol[i];
            split4(rU[i], h, l);
            *(uint4*)(UH + off) = h;
            *(uint4*)(UL + off) = l;
            split4(rX[i], h, l);
            *(uint4*)(XH + off) = h;
            *(uint4*)(XL + off) = l;
        }
        __syncthreads();

        // prefetch next stage
        if (s + 1 < NST1) {
            #pragma unroll
            for (int i = 0; i < 4; i++) {
                int n = n0 + (s + 1) * 32 + lrow[i];
                if (n < N_NODES) {
                    rU[i] = *(const float4*)(U + (size_t)n * K_EIG + kt * 128 + lcol[i]);
                    rX[i] = *(const float4*)(x + (size_t)n * F_DIM + lcol[i]);
                } else {
                    rU[i] = make_float4(0.f, 0.f, 0.f, 0.f);
                    rX[i] = rU[i];
                }
            }
        }

        // MMA over this stage
        #pragma unroll
        for (int r0 = 0; r0 < 32; r0 += 8) {
            const int ra = (r0 + qc) * STR1;
            const int rb = (r0 + 4 + qc) * STR1;
            unsigned ah[4][4], al[4][4], bh[4][2], bl[4][2];
            #pragma unroll
            for (int mt = 0; mt < 4; mt++) {
                int m = wm * 64 + mt * 16 + qr;
                ah[mt][0] = UH[ra + m];     al[mt][0] = UL[ra + m];
                ah[mt][1] = UH[ra + m + 8]; al[mt][1] = UL[ra + m + 8];
                ah[mt][2] = UH[rb + m];     al[mt][2] = UL[rb + m];
                ah[mt][3] = UH[rb + m + 8]; al[mt][3] = UL[rb + m + 8];
            }
            #pragma unroll
            for (int nt = 0; nt < 4; nt++) {
                int f = wf * 32 + nt * 8 + qr;
                bh[nt][0] = XH[ra + f]; bl[nt][0] = XL[ra + f];
                bh[nt][1] = XH[rb + f]; bl[nt][1] = XL[rb + f];
            }
            #pragma unroll
            for (int mt = 0; mt < 4; mt++)
                #pragma unroll
                for (int nt = 0; nt < 4; nt++) {
                    mma8(acc[mt][nt], al[mt][0], al[mt][1], al[mt][2], al[mt][3],
                         bh[nt][0], bh[nt][1]);
                    mma8(acc[mt][nt], ah[mt][0], ah[mt][1], ah[mt][2], ah[mt][3],
                         bl[nt][0], bl[nt][1]);
                    mma8(acc[mt][nt], ah[mt][0], ah[mt][1], ah[mt][2], ah[mt][3],
                         bh[nt][0], bh[nt][1]);
                }
        }
        __syncthreads();
    }

    float* pbase = g_partial + (size_t)ch * (K_EIG * F_DIM);
    #pragma unroll
    for (int mt = 0; mt < 4; mt++) {
        int m = wm * 64 + mt * 16 + qr;
        #pragma unroll
        for (int nt = 0; nt < 4; nt++) {
            int f  = wf * 32 + nt * 8 + 2 * qc;
            int kq = kt * 128 + m;
            *(float2*)(pbase + (size_t)kq * F_DIM + f) =
                make_float2(acc[mt][nt][0], acc[mt][nt][1]);
            *(float2*)(pbase + (size_t)(kq + 8) * F_DIM + f) =
                make_float2(acc[mt][nt][2], acc[mt][nt][3]);
        }
    }
}

// ---------------------------------------------------------------------------
// Phase 1.5: y = g[k] * sum_ch partial; pre-split into tf32 hi/lo planes.
// ---------------------------------------------------------------------------
__global__ void phase15_kernel(const float* __restrict__ g) {
    int idx = blockIdx.x * blockDim.x + threadIdx.x;
    float s = 0.f;
    #pragma unroll 37
    for (int c = 0; c < NC; c++)
        s += g_partial[(size_t)c * (K_EIG * F_DIM) + idx];
    s *= __ldg(&g[idx >> 7]);
    unsigned h, l;
    split_tf32(s, h, l);
    g_yhi[idx] = h;
    g_ylo[idx] = l;
}

// ---------------------------------------------------------------------------
// Phase 2: out[n][f] = relu( sum_k U[n,k] * y[k,f] )
// 391 CTAs, tile 128(n) x 128(f); same pipelined structure. Y arrives
// pre-split (raw copy), only U is split at fill time.
// ---------------------------------------------------------------------------
__global__ void __launch_bounds__(256)
phase2_kernel(const float* __restrict__ U, float* __restrict__ out) {
    extern __shared__ unsigned sm[];

    const int nb   = blockIdx.x * 128;
    const int tid  = threadIdx.x;
    const int lane = tid & 31;
    const int wid  = tid >> 5;
    const int wm   = wid >> 2;
    const int wf   = wid & 3;
    const int qr   = lane >> 2;
    const int qc   = lane & 3;

    // U loader coords (128 rows x 32 cols)
    int urow[4], ucol[4];
    // Y loader coords (32 rows x 128 cols)
    int yrow[4], ycol[4];
    #pragma unroll
    for (int i = 0; i < 4; i++) {
        int e = tid + i * 256;
        urow[i] = e >> 3;
        ucol[i] = (e & 7) << 2;
        yrow[i] = e >> 5;
        ycol[i] = (e & 31) << 2;
    }

    float acc[4][4][4];
    #pragma unroll
    for (int a = 0; a < 4; a++)
        #pragma unroll
        for (int b = 0; b < 4; b++)
            #pragma unroll
            for (int c = 0; c < 4; c++) acc[a][b][c] = 0.f;

    float4 rU[4];
    uint4  rYh[4], rYl[4];

    #pragma unroll
    for (int i = 0; i < 4; i++) {
        int n = nb + urow[i];
        rU[i] = (n < N_NODES)
              ? *(const float4*)(U + (size_t)n * K_EIG + ucol[i])
              : make_float4(0.f, 0.f, 0.f, 0.f);
        rYh[i] = *(const uint4*)(g_yhi + (size_t)yrow[i] * F_DIM + ycol[i]);
        rYl[i] = *(const uint4*)(g_ylo + (size_t)yrow[i] * F_DIM + ycol[i]);
    }

    const int NST2 = K_EIG / 32;   // 16
    for (int s = 0; s < NST2; s++) {
        unsigned* base = sm + (s & 1) * STG2;
        unsigned* UH = base;
        unsigned* UL = base + USZ2;
        unsigned* YH = base + 2 * USZ2;
        unsigned* YL = base + 2 * USZ2 + YSZ2;

        #pragma unroll
        for (int i = 0; i < 4; i++) {
            uint4 h, l;
            split4(rU[i], h, l);
            int off = urow[i] * STRU2 + ucol[i];
            *(uint4*)(UH + off) = h;
            *(uint4*)(UL + off) = l;
            int yoff = yrow[i] * STR1 + ycol[i];
            *(uint4*)(YH + yoff) = rYh[i];
            *(uint4*)(YL + yoff) = rYl[i];
        }
        __syncthreads();

        if (s + 1 < NST2) {
            int kk = (s + 1) * 32;
            #pragma unroll
            for (int i = 0; i < 4; i++) {
                int n = nb + urow[i];
                rU[i] = (n < N_NODES)
                      ? *(const float4*)(U + (size_t)n * K_EIG + kk + ucol[i])
                      : make_float4(0.f, 0.f, 0.f, 0.f);
                rYh[i] = *(const uint4*)(g_yhi + (size_t)(kk + yrow[i]) * F_DIM + ycol[i]);
                rYl[i] = *(const uint4*)(g_ylo + (size_t)(kk + yrow[i]) * F_DIM + ycol[i]);
            }
        }

        #pragma unroll
        for (int r0 = 0; r0 < 32; r0 += 8) {
            const int ca = r0 + qc;
            const int cb = r0 + 4 + qc;
            unsigned ah[4][4], al[4][4], bh[4][2], bl[4][2];
            #pragma unroll
            for (int mt = 0; mt < 4; mt++) {
                int m  = wm * 64 + mt * 16 + qr;
                int o0 = m * STRU2;
                int o1 = (m + 8) * STRU2;
                ah[mt][0] = UH[o0 + ca]; al[mt][0] = UL[o0 + ca];
                ah[mt][1] = UH[o1 + ca]; al[mt][1] = UL[o1 + ca];
                ah[mt][2] = UH[o0 + cb]; al[mt][2] = UL[o0 + cb];
                ah[mt][3] = UH[o1 + cb]; al[mt][3] = UL[o1 + cb];
            }
            #pragma unroll
            for (int nt = 0; nt < 4; nt++) {
                int f = wf * 32 + nt * 8 + qr;
                bh[nt][0] = YH[ca * STR1 + f]; bl[nt][0] = YL[ca * STR1 + f];
                bh[nt][1] = YH[cb * STR1 + f]; bl[nt][1] = YL[cb * STR1 + f];
            }
            #pragma unroll
            for (int mt = 0; mt < 4; mt++)
                #pragma unroll
                for (int nt = 0; nt < 4; nt++) {
                    mma8(acc[mt][nt], al[mt][0], al[mt][1], al[mt][2], al[mt][3],
                         bh[nt][0], bh[nt][1]);
                    mma8(acc[mt][nt], ah[mt][0], ah[mt][1], ah[mt][2], ah[mt][3],
                         bl[nt][0], bl[nt][1]);
                    mma8(acc[mt][nt], ah[mt][0], ah[mt][1], ah[mt][2], ah[mt][3],
                         bh[nt][0], bh[nt][1]);
                }
        }
        __syncthreads();
    }

    #pragma unroll
    for (int mt = 0; mt < 4; mt++) {
        int n = nb + wm * 64 + mt * 16 + qr;
        #pragma unroll
        for (int nt = 0; nt < 4; nt++) {
            int f = wf * 32 + nt * 8 + 2 * qc;
            if (n < N_NODES) {
                *(float2*)(out + (size_t)n * F_DIM + f) =
                    make_float2(fmaxf(acc[mt][nt][0], 0.f),
                                fmaxf(acc[mt][nt][1], 0.f));
            }
            if (n + 8 < N_NODES) {
                *(float2*)(out + (size_t)(n + 8) * F_DIM + f) =
                    make_float2(fmaxf(acc[mt][nt][2], 0.f),
                                fmaxf(acc[mt][nt][3], 0.f));
            }
        }
    }
}

// ---------------------------------------------------------------------------
extern "C" void kernel_launch(void* const* d_in, const int* in_sizes, int n_in,
                              void* d_out, int out_size) {
    const float* U = nullptr;
    const float* g = nullptr;
    const float* x = nullptr;
    for (int i = 0; i < n_in; i++) {
        if (in_sizes[i] == N_NODES * K_EIG)      U = (const float*)d_in[i];
        else if (in_sizes[i] == K_EIG)           g = (const float*)d_in[i];
        else if (in_sizes[i] == N_NODES * F_DIM) x = (const float*)d_in[i];
    }
    float* out = (float*)d_out;

    cudaFuncSetAttribute(phase1_kernel,
                         cudaFuncAttributeMaxDynamicSharedMemorySize, P1_SMEM);
    cudaFuncSetAttribute(phase2_kernel,
                         cudaFuncAttributeMaxDynamicSharedMemorySize, P2_SMEM);

    phase1_kernel<<<dim3(4, NC), 256, P1_SMEM>>>(U, x);
    phase15_kernel<<<(K_EIG * F_DIM) / 256, 256>>>(g);
    phase2_kernel<<<(N_NODES + 127) / 128, 256, P2_SMEM>>>(U, out);
}

// round 4
// speedup vs baseline: 2.4353x; 1.5645x over previous
#include <cuda_runtime.h>
#include <cuda_bf16.h>
#include <cstdint>
#include <cstddef>

#define N_NODES 50000
#define K_EIG   512
#define F_DIM   128
#define CH      1376      // 43 stages of 32 rows
#define NC      37        // 4 x 37 = 148 CTAs = one wave
#define NST1    43

// phase1 smem plane geometry (bf16 element units)
#define P1_STR  136                 // row stride: 272B -> ldmatrix conflict-free
#define P1_ASZ  (32 * P1_STR)       // 4352 bf16 per 32x128 plane
#define P1_STG  (4 * P1_ASZ)        // UH,UL,XH,XL
#define P1_SMEM (2 * P1_STG * 2)    // 69632 B

// phase2 smem
#define P2_USTR 40                  // 80B -> conflict-free ldmatrix
#define P2_USZ  (128 * P2_USTR)     // 5120
#define P2_YSTR 136
#define P2_YSZ  (32 * P2_YSTR)      // 4352
#define P2_STG  (2 * P2_USZ + 2 * P2_YSZ)   // 18944 bf16
#define P2_SMEM (2 * P2_STG * 2)    // 75776 B

// Scratch (__device__ globals per allocation-free rule)
__device__ float          g_partial[(size_t)NC * K_EIG * F_DIM];
__device__ __nv_bfloat16  g_yh[K_EIG * F_DIM];
__device__ __nv_bfloat16  g_yl[K_EIG * F_DIM];

// ---------------------------------------------------------------------------
__device__ __forceinline__ unsigned pack2(__nv_bfloat16 a, __nv_bfloat16 b) {
    return ((unsigned)__bfloat16_as_ushort(b) << 16) | __bfloat16_as_ushort(a);
}

// split float pair -> packed bf16 hi-pair + lo-pair
__device__ __forceinline__ void split2(float a, float b, unsigned &hp, unsigned &lp) {
    __nv_bfloat16 ha = __float2bfloat16_rn(a);
    __nv_bfloat16 hb = __float2bfloat16_rn(b);
    __nv_bfloat16 la = __float2bfloat16_rn(a - __bfloat162float(ha));
    __nv_bfloat16 lb = __float2bfloat16_rn(b - __bfloat162float(hb));
    hp = pack2(ha, hb);
    lp = pack2(la, lb);
}

__device__ __forceinline__ void split4(float4 v, uint2 &h, uint2 &l) {
    split2(v.x, v.y, h.x, l.x);
    split2(v.z, v.w, h.y, l.y);
}

#define LDSM_T(R, addr) \
    asm volatile("ldmatrix.sync.aligned.m8n8.x4.trans.shared.b16 {%0,%1,%2,%3}, [%4];" \
                 : "=r"((R)[0]), "=r"((R)[1]), "=r"((R)[2]), "=r"((R)[3]) : "r"(addr))

#define LDSM_N(R, addr) \
    asm volatile("ldmatrix.sync.aligned.m8n8.x4.shared.b16 {%0,%1,%2,%3}, [%4];" \
                 : "=r"((R)[0]), "=r"((R)[1]), "=r"((R)[2]), "=r"((R)[3]) : "r"(addr))

#define MMA16(C, A, B0, B1) \
    asm volatile("mma.sync.aligned.m16n8k16.row.col.f32.bf16.bf16.f32 " \
                 "{%0,%1,%2,%3},{%4,%5,%6,%7},{%8,%9},{%0,%1,%2,%3};" \
                 : "+f"((C)[0]), "+f"((C)[1]), "+f"((C)[2]), "+f"((C)[3]) \
                 : "r"((A)[0]), "r"((A)[1]), "r"((A)[2]), "r"((A)[3]), \
                   "r"(B0), "r"(B1))

// ---------------------------------------------------------------------------
// Phase 1: partial[ch][k][f] = sum_{n in chunk} U[n,k] * x[n,f]
// Grid (4,37)=148 CTAs. CTA tile 128(k) x 128(f). bf16x2 split, ldmatrix.trans.
// ---------------------------------------------------------------------------
__global__ void __launch_bounds__(256)
phase1_kernel(const float* __restrict__ U, const float* __restrict__ x) {
    extern __shared__ unsigned short smw[];
    const unsigned sbase = (unsigned)__cvta_generic_to_shared(smw);

    const int kt   = blockIdx.x;
    const int ch   = blockIdx.y;
    const int tid  = threadIdx.x;
    const int lane = tid & 31;
    const int wid  = tid >> 5;
    const int wm   = wid >> 2;
    const int wf   = wid & 3;
    const int n0   = ch * CH;

    int lrow[4], lcol[4];
    #pragma unroll
    for (int i = 0; i < 4; i++) {
        int e = tid + i * 256;
        lrow[i] = e >> 5;
        lcol[i] = (e & 31) << 2;
    }

    // ldmatrix per-lane fragment offsets (element units)
    const int lr   = lane & 7;
    const int arow = ((lane >> 4) & 1) * 8 + lr;
    const int acol = ((lane >> 3) & 1) * 8;
    const int brow = ((lane >> 3) & 1) * 8 + lr;
    const int bcol = ((lane >> 4) & 1) * 8;
    unsigned aoffs[4], boffs[2];
    #pragma unroll
    for (int mt = 0; mt < 4; mt++)
        aoffs[mt] = arow * P1_STR + wm * 64 + mt * 16 + acol;
    #pragma unroll
    for (int blk = 0; blk < 2; blk++)
        boffs[blk] = brow * P1_STR + wf * 32 + blk * 16 + bcol;

    float acc[4][4][4];
    #pragma unroll
    for (int a = 0; a < 4; a++)
        #pragma unroll
        for (int b = 0; b < 4; b++)
            #pragma unroll
            for (int c = 0; c < 4; c++) acc[a][b][c] = 0.f;

    float4 rU[4], rX[4];
    #pragma unroll
    for (int i = 0; i < 4; i++) {
        int n = n0 + lrow[i];
        if (n < N_NODES) {
            rU[i] = *(const float4*)(U + (size_t)n * K_EIG + kt * 128 + lcol[i]);
            rX[i] = *(const float4*)(x + (size_t)n * F_DIM + lcol[i]);
        } else {
            rU[i] = make_float4(0.f, 0.f, 0.f, 0.f);
            rX[i] = rU[i];
        }
    }

    for (int s = 0; s < NST1; s++) {
        unsigned short* st = smw + (s & 1) * P1_STG;
        #pragma unroll
        for (int i = 0; i < 4; i++) {
            uint2 h, l;
            int off = lrow[i] * P1_STR + lcol[i];
            split4(rU[i], h, l);
            *(uint2*)(st + off)          = h;            // UH
            *(uint2*)(st + P1_ASZ + off) = l;            // UL
            split4(rX[i], h, l);
            *(uint2*)(st + 2 * P1_ASZ + off) = h;        // XH
            *(uint2*)(st + 3 * P1_ASZ + off) = l;        // XL
        }
        __syncthreads();

        if (s + 1 < NST1) {
            #pragma unroll
            for (int i = 0; i < 4; i++) {
                int n = n0 + (s + 1) * 32 + lrow[i];
                if (n < N_NODES) {
                    rU[i] = *(const float4*)(U + (size_t)n * K_EIG + kt * 128 + lcol[i]);
                    rX[i] = *(const float4*)(x + (size_t)n * F_DIM + lcol[i]);
                } else {
                    rU[i] = make_float4(0.f, 0.f, 0.f, 0.f);
                    rX[i] = rU[i];
                }
            }
        }

        const unsigned stg = (s & 1) * P1_STG;
        #pragma unroll
        for (int c = 0; c < 2; c++) {
            const unsigned nco = stg + c * 16 * P1_STR;
            unsigned ah[4][4], al[4][4], bh[4][2], bl[4][2];
            #pragma unroll
            for (int mt = 0; mt < 4; mt++) {
                LDSM_T(ah[mt], sbase + (nco + aoffs[mt]) * 2);
                LDSM_T(al[mt], sbase + (nco + P1_ASZ + aoffs[mt]) * 2);
            }
            #pragma unroll
            for (int blk = 0; blk < 2; blk++) {
                unsigned t[4];
                LDSM_T(t, sbase + (nco + 2 * P1_ASZ + boffs[blk]) * 2);
                bh[blk * 2][0] = t[0]; bh[blk * 2][1] = t[1];
                bh[blk * 2 + 1][0] = t[2]; bh[blk * 2 + 1][1] = t[3];
                LDSM_T(t, sbase + (nco + 3 * P1_ASZ + boffs[blk]) * 2);
                bl[blk * 2][0] = t[0]; bl[blk * 2][1] = t[1];
                bl[blk * 2 + 1][0] = t[2]; bl[blk * 2 + 1][1] = t[3];
            }
            #pragma unroll
            for (int mt = 0; mt < 4; mt++)
                #pragma unroll
                for (int nt = 0; nt < 4; nt++) {
                    MMA16(acc[mt][nt], al[mt], bh[nt][0], bh[nt][1]);
                    MMA16(acc[mt][nt], ah[mt], bl[nt][0], bl[nt][1]);
                    MMA16(acc[mt][nt], ah[mt], bh[nt][0], bh[nt][1]);
                }
        }
        __syncthreads();
    }

    const int qr = lane >> 2, qc = lane & 3;
    float* pbase = g_partial + (size_t)ch * (K_EIG * F_DIM);
    #pragma unroll
    for (int mt = 0; mt < 4; mt++) {
        int m = wm * 64 + mt * 16 + qr;
        #pragma unroll
        for (int nt = 0; nt < 4; nt++) {
            int f  = wf * 32 + nt * 8 + 2 * qc;
            int kq = kt * 128 + m;
            __stwt((float2*)(pbase + (size_t)kq * F_DIM + f),
                   make_float2(acc[mt][nt][0], acc[mt][nt][1]));
            __stwt((float2*)(pbase + (size_t)(kq + 8) * F_DIM + f),
                   make_float2(acc[mt][nt][2], acc[mt][nt][3]));
        }
    }
}

// ---------------------------------------------------------------------------
// Phase 1.5: y = g[k]*sum_ch partial -> pre-split bf16 hi/lo planes [k][f]
// Vectorized float4: 16384 threads, each reduces one float4 column strip.
// ---------------------------------------------------------------------------
__global__ void phase15_kernel(const float* __restrict__ g) {
    int v = blockIdx.x * blockDim.x + threadIdx.x;     // 0..16383 (float4 idx)
    int idx = v * 4;
    float4 s = make_float4(0.f, 0.f, 0.f, 0.f);
    #pragma unroll 37
    for (int c = 0; c < NC; c++) {
        float4 p = *(const float4*)(g_partial + (size_t)c * (K_EIG * F_DIM) + idx);
        s.x += p.x; s.y += p.y; s.z += p.z; s.w += p.w;
    }
    float gk = __ldg(&g[idx >> 7]);   // 4 consecutive f share one k
    s.x *= gk; s.y *= gk; s.z *= gk; s.w *= gk;

    __nv_bfloat16 h[4], l[4];
    float sv[4] = {s.x, s.y, s.z, s.w};
    #pragma unroll
    for (int i = 0; i < 4; i++) {
        h[i] = __float2bfloat16_rn(sv[i]);
        l[i] = __float2bfloat16_rn(sv[i] - __bfloat162float(h[i]));
    }
    *(uint2*)(g_yh + idx) = make_uint2(pack2(h[0], h[1]), pack2(h[2], h[3]));
    *(uint2*)(g_yl + idx) = make_uint2(pack2(l[0], l[1]), pack2(l[2], l[3]));
}

// ---------------------------------------------------------------------------
// Phase 2: out[n][f] = relu( sum_k U[n,k] * y[k,f] )
// 391 CTAs, tile 128x128. A: non-trans ldmatrix; B: trans ldmatrix.
// ---------------------------------------------------------------------------
__global__ void __launch_bounds__(256)
phase2_kernel(const float* __restrict__ U, float* __restrict__ out) {
    extern __shared__ unsigned short smw[];
    const unsigned sbase = (unsigned)__cvta_generic_to_shared(smw);

    const int nb   = blockIdx.x * 128;
    const int tid  = threadIdx.x;
    const int lane = tid & 31;
    const int wid  = tid >> 5;
    const int wm   = wid >> 2;
    const int wf   = wid & 3;

    int urow[4], ucol[4], yrow[4], ycol[4];
    #pragma unroll
    for (int i = 0; i < 4; i++) {
        int e = tid + i * 256;
        urow[i] = e >> 3;
        ucol[i] = (e & 7) << 2;
        yrow[i] = e >> 5;
        ycol[i] = (e & 31) << 2;
    }

    const int lr   = lane & 7;
    const int arow = ((lane >> 3) & 1) * 8 + lr;       // non-trans A
    const int acol = ((lane >> 4) & 1) * 8;
    const int brow = ((lane >> 3) & 1) * 8 + lr;       // trans B
    const int bcol = ((lane >> 4) & 1) * 8;
    unsigned aoffs[4], boffs[2];
    #pragma unroll
    for (int mt = 0; mt < 4; mt++)
        aoffs[mt] = (unsigned)((wm * 64 + mt * 16 + arow) * P2_USTR + acol);
    #pragma unroll
    for (int blk = 0; blk < 2; blk++)
        boffs[blk] = (unsigned)(brow * P2_YSTR + wf * 32 + blk * 16 + bcol);

    float acc[4][4][4];
    #pragma unroll
    for (int a = 0; a < 4; a++)
        #pragma unroll
        for (int b = 0; b < 4; b++)
            #pragma unroll
            for (int c = 0; c < 4; c++) acc[a][b][c] = 0.f;

    float4 rU[4];
    uint2  rYh[4], rYl[4];
    #pragma unroll
    for (int i = 0; i < 4; i++) {
        int n = nb + urow[i];
        rU[i] = (n < N_NODES)
              ? *(const float4*)(U + (size_t)n * K_EIG + ucol[i])
              : make_float4(0.f, 0.f, 0.f, 0.f);
        rYh[i] = *(const uint2*)(g_yh + (size_t)yrow[i] * F_DIM + ycol[i]);
        rYl[i] = *(const uint2*)(g_yl + (size_t)yrow[i] * F_DIM + ycol[i]);
    }

    const int NST2 = K_EIG / 32;
    for (int s = 0; s < NST2; s++) {
        unsigned short* st = smw + (s & 1) * P2_STG;
        #pragma unroll
        for (int i = 0; i < 4; i++) {
            uint2 h, l;
            split4(rU[i], h, l);
            int uoff = urow[i] * P2_USTR + ucol[i];
            *(uint2*)(st + uoff)           = h;                    // UH
            *(uint2*)(st + P2_USZ + uoff)  = l;                    // UL
            int yoff = yrow[i] * P2_YSTR + ycol[i];
            *(uint2*)(st + 2 * P2_USZ + yoff)           = rYh[i];  // YH
            *(uint2*)(st + 2 * P2_USZ + P2_YSZ + yoff)  = rYl[i];  // YL
        }
        __syncthreads();

        if (s + 1 < NST2) {
            int kk = (s + 1) * 32;
            #pragma unroll
            for (int i = 0; i < 4; i++) {
                int n = nb + urow[i];
                rU[i] = (n < N_NODES)
                      ? *(const float4*)(U + (size_t)n * K_EIG + kk + ucol[i])
                      : make_float4(0.f, 0.f, 0.f, 0.f);
                rYh[i] = *(const uint2*)(g_yh + (size_t)(kk + yrow[i]) * F_DIM + ycol[i]);
                rYl[i] = *(const uint2*)(g_yl + (size_t)(kk + yrow[i]) * F_DIM + ycol[i]);
            }
        }

        const unsigned stg = (s & 1) * P2_STG;
        #pragma unroll
        for (int c = 0; c < 2; c++) {
            unsigned ah[4][4], al[4][4], bh[4][2], bl[4][2];
            #pragma unroll
            for (int mt = 0; mt < 4; mt++) {
                LDSM_N(ah[mt], sbase + (stg + aoffs[mt] + c * 16) * 2);
                LDSM_N(al[mt], sbase + (stg + P2_USZ + aoffs[mt] + c * 16) * 2);
            }
            #pragma unroll
            for (int blk = 0; blk < 2; blk++) {
                unsigned t[4];
                LDSM_T(t, sbase + (stg + 2 * P2_USZ + c * 16 * P2_YSTR + boffs[blk]) * 2);
                bh[blk * 2][0] = t[0]; bh[blk * 2][1] = t[1];
                bh[blk * 2 + 1][0] = t[2]; bh[blk * 2 + 1][1] = t[3];
                LDSM_T(t, sbase + (stg + 2 * P2_USZ + P2_YSZ + c * 16 * P2_YSTR + boffs[blk]) * 2);
                bl[blk * 2][0] = t[0]; bl[blk * 2][1] = t[1];
                bl[blk * 2 + 1][0] = t[2]; bl[blk * 2 + 1][1] = t[3];
            }
            #pragma unroll
            for (int mt = 0; mt < 4; mt++)
                #pragma unroll
                for (int nt = 0; nt < 4; nt++) {
                    MMA16(acc[mt][nt], al[mt], bh[nt][0], bh[nt][1]);
                    MMA16(acc[mt][nt], ah[mt], bl[nt][0], bl[nt][1]);
                    MMA16(acc[mt][nt], ah[mt], bh[nt][0], bh[nt][1]);
                }
        }
        __syncthreads();
    }

    const int qr = lane >> 2, qc = lane & 3;
    #pragma unroll
    for (int mt = 0; mt < 4; mt++) {
        int n = nb + wm * 64 + mt * 16 + qr;
        #pragma unroll
        for (int nt = 0; nt < 4; nt++) {
            int f = wf * 32 + nt * 8 + 2 * qc;
            if (n < N_NODES) {
                *(float2*)(out + (size_t)n * F_DIM + f) =
                    make_float2(fmaxf(acc[mt][nt][0], 0.f),
                                fmaxf(acc[mt][nt][1], 0.f));
            }
            if (n + 8 < N_NODES) {
                *(float2*)(out + (size_t)(n + 8) * F_DIM + f) =
                    make_float2(fmaxf(acc[mt][nt][2], 0.f),
                                fmaxf(acc[mt][nt][3], 0.f));
            }
        }
    }
}

// ---------------------------------------------------------------------------
extern "C" void kernel_launch(void* const* d_in, const int* in_sizes, int n_in,
                              void* d_out, int out_size) {
    const float* U = nullptr;
    const float* g = nullptr;
    const float* x = nullptr;
    for (int i = 0; i < n_in; i++) {
        if (in_sizes[i] == N_NODES * K_EIG)      U = (const float*)d_in[i];
        else if (in_sizes[i] == K_EIG)           g = (const float*)d_in[i];
        else if (in_sizes[i] == N_NODES * F_DIM) x = (const float*)d_in[i];
    }
    float* out = (float*)d_out;

    cudaFuncSetAttribute(phase1_kernel,
                         cudaFuncAttributeMaxDynamicSharedMemorySize, P1_SMEM);
    cudaFuncSetAttribute(phase2_kernel,
                         cudaFuncAttributeMaxDynamicSharedMemorySize, P2_SMEM);

    phase1_kernel<<<dim3(4, NC), 256, P1_SMEM>>>(U, x);
    phase15_kernel<<<(K_EIG * F_DIM) / 1024, 256>>>(g);
    phase2_kernel<<<(N_NODES + 127) / 128, 256, P2_SMEM>>>(U, out);
}

// round 5
// speedup vs baseline: 2.4430x; 1.0032x over previous
#include <cuda_runtime.h>
#include <cuda_bf16.h>
#include <cstdint>
#include <cstddef>

#define N_NODES 50000
#define K_EIG   512
#define F_DIM   128
#define CH      1376      // 43 stages of 32 rows
#define NC      37        // 4 x 37 = 148 CTAs = one wave
#define NST1    43

// phase1 smem plane geometry (bf16 element units)
#define P1_STR  136                 // 272B row stride -> ldmatrix conflict-free
#define P1_ASZ  (32 * P1_STR)
#define P1_STG  (4 * P1_ASZ)        // UH,UL,XH,XL
#define P1_SMEM (2 * P1_STG * 2)    // 69632 B

// phase2 smem
#define P2_USTR 40
#define P2_USZ  (128 * P2_USTR)
#define P2_YSTR 136
#define P2_YSZ  (32 * P2_YSTR)
#define P2_STG  (2 * P2_USZ + 2 * P2_YSZ)
#define P2_SMEM (2 * P2_STG * 2)    // 75776 B

__device__ float          g_partial[(size_t)NC * K_EIG * F_DIM];
__device__ __nv_bfloat16  g_yh[K_EIG * F_DIM];
__device__ __nv_bfloat16  g_yl[K_EIG * F_DIM];

// ---------------------------------------------------------------------------
__device__ __forceinline__ unsigned pack2(__nv_bfloat16 a, __nv_bfloat16 b) {
    return ((unsigned)__bfloat16_as_ushort(b) << 16) | __bfloat16_as_ushort(a);
}

__device__ __forceinline__ void split2(float a, float b, unsigned &hp, unsigned &lp) {
    __nv_bfloat16 ha = __float2bfloat16_rn(a);
    __nv_bfloat16 hb = __float2bfloat16_rn(b);
    __nv_bfloat16 la = __float2bfloat16_rn(a - __bfloat162float(ha));
    __nv_bfloat16 lb = __float2bfloat16_rn(b - __bfloat162float(hb));
    hp = pack2(ha, hb);
    lp = pack2(la, lb);
}

__device__ __forceinline__ void split4(float4 v, uint2 &h, uint2 &l) {
    split2(v.x, v.y, h.x, l.x);
    split2(v.z, v.w, h.y, l.y);
}

#define LDSM_T(R, addr) \
    asm volatile("ldmatrix.sync.aligned.m8n8.x4.trans.shared.b16 {%0,%1,%2,%3}, [%4];" \
                 : "=r"((R)[0]), "=r"((R)[1]), "=r"((R)[2]), "=r"((R)[3]) : "r"(addr))

#define LDSM_N(R, addr) \
    asm volatile("ldmatrix.sync.aligned.m8n8.x4.shared.b16 {%0,%1,%2,%3}, [%4];" \
                 : "=r"((R)[0]), "=r"((R)[1]), "=r"((R)[2]), "=r"((R)[3]) : "r"(addr))

#define MMA16(C, A, B0, B1) \
    asm volatile("mma.sync.aligned.m16n8k16.row.col.f32.bf16.bf16.f32 " \
                 "{%0,%1,%2,%3},{%4,%5,%6,%7},{%8,%9},{%0,%1,%2,%3};" \
                 : "+f"((C)[0]), "+f"((C)[1]), "+f"((C)[2]), "+f"((C)[3]) \
                 : "r"((A)[0]), "r"((A)[1]), "r"((A)[2]), "r"((A)[3]), \
                   "r"(B0), "r"(B1))

// ---------------------------------------------------------------------------
// Phase 1: partial[ch][k][f] = sum_{n in chunk} U[n,k] * x[n,f]
// Grid (4,37)=148 CTAs, 512 threads (16 warps), warp tile 32(k) x 32(f).
// ---------------------------------------------------------------------------
__global__ void __launch_bounds__(512)
phase1_kernel(const float* __restrict__ U, const float* __restrict__ x) {
    extern __shared__ unsigned short smw[];
    const unsigned sbase = (unsigned)__cvta_generic_to_shared(smw);

    const int kt   = blockIdx.x;
    const int ch   = blockIdx.y;
    const int tid  = threadIdx.x;
    const int lane = tid & 31;
    const int wid  = tid >> 5;
    const int wm   = wid >> 2;            // 0..3 (k 32-strips)
    const int wf   = wid & 3;             // 0..3 (f 32-strips)
    const int n0   = ch * CH;

    int lrow[2], lcol[2];
    #pragma unroll
    for (int i = 0; i < 2; i++) {
        int e = tid + i * 512;            // 0..1023
        lrow[i] = e >> 5;
        lcol[i] = (e & 31) << 2;
    }

    const int lr   = lane & 7;
    const int arow = ((lane >> 4) & 1) * 8 + lr;
    const int acol = ((lane >> 3) & 1) * 8;
    const int brow = ((lane >> 3) & 1) * 8 + lr;
    const int bcol = ((lane >> 4) & 1) * 8;
    unsigned aoffs[2], boffs[2];
    #pragma unroll
    for (int mt = 0; mt < 2; mt++)
        aoffs[mt] = arow * P1_STR + wm * 32 + mt * 16 + acol;
    #pragma unroll
    for (int blk = 0; blk < 2; blk++)
        boffs[blk] = brow * P1_STR + wf * 32 + blk * 16 + bcol;

    float acc[2][4][4];
    #pragma unroll
    for (int a = 0; a < 2; a++)
        #pragma unroll
        for (int b = 0; b < 4; b++)
            #pragma unroll
            for (int c = 0; c < 4; c++) acc[a][b][c] = 0.f;

    float4 rU[2], rX[2];
    #pragma unroll
    for (int i = 0; i < 2; i++) {
        int n = n0 + lrow[i];
        if (n < N_NODES) {
            rU[i] = *(const float4*)(U + (size_t)n * K_EIG + kt * 128 + lcol[i]);
            rX[i] = *(const float4*)(x + (size_t)n * F_DIM + lcol[i]);
        } else {
            rU[i] = make_float4(0.f, 0.f, 0.f, 0.f);
            rX[i] = rU[i];
        }
    }

    for (int s = 0; s < NST1; s++) {
        unsigned short* st = smw + (s & 1) * P1_STG;
        #pragma unroll
        for (int i = 0; i < 2; i++) {
            uint2 h, l;
            int off = lrow[i] * P1_STR + lcol[i];
            split4(rU[i], h, l);
            *(uint2*)(st + off)          = h;            // UH
            *(uint2*)(st + P1_ASZ + off) = l;            // UL
            split4(rX[i], h, l);
            *(uint2*)(st + 2 * P1_ASZ + off) = h;        // XH
            *(uint2*)(st + 3 * P1_ASZ + off) = l;        // XL
        }
        __syncthreads();

        if (s + 1 < NST1) {
            #pragma unroll
            for (int i = 0; i < 2; i++) {
                int n = n0 + (s + 1) * 32 + lrow[i];
                if (n < N_NODES) {
                    rU[i] = *(const float4*)(U + (size_t)n * K_EIG + kt * 128 + lcol[i]);
                    rX[i] = *(const float4*)(x + (size_t)n * F_DIM + lcol[i]);
                } else {
                    rU[i] = make_float4(0.f, 0.f, 0.f, 0.f);
                    rX[i] = rU[i];
                }
            }
        }

        const unsigned stg = (s & 1) * P1_STG;
        #pragma unroll
        for (int c = 0; c < 2; c++) {
            const unsigned nco = stg + c * 16 * P1_STR;
            unsigned ah[2][4], al[2][4], bh[4][2], bl[4][2];
            #pragma unroll
            for (int mt = 0; mt < 2; mt++) {
                LDSM_T(ah[mt], sbase + (nco + aoffs[mt]) * 2);
                LDSM_T(al[mt], sbase + (nco + P1_ASZ + aoffs[mt]) * 2);
            }
            #pragma unroll
            for (int blk = 0; blk < 2; blk++) {
                unsigned t[4];
                LDSM_T(t, sbase + (nco + 2 * P1_ASZ + boffs[blk]) * 2);
                bh[blk * 2][0] = t[0]; bh[blk * 2][1] = t[1];
                bh[blk * 2 + 1][0] = t[2]; bh[blk * 2 + 1][1] = t[3];
                LDSM_T(t, sbase + (nco + 3 * P1_ASZ + boffs[blk]) * 2);
                bl[blk * 2][0] = t[0]; bl[blk * 2][1] = t[1];
                bl[blk * 2 + 1][0] = t[2]; bl[blk * 2 + 1][1] = t[3];
            }
            #pragma unroll
            for (int mt = 0; mt < 2; mt++)
                #pragma unroll
                for (int nt = 0; nt < 4; nt++) {
                    MMA16(acc[mt][nt], al[mt], bh[nt][0], bh[nt][1]);
                    MMA16(acc[mt][nt], ah[mt], bl[nt][0], bl[nt][1]);
                    MMA16(acc[mt][nt], ah[mt], bh[nt][0], bh[nt][1]);
                }
        }
        __syncthreads();
    }

    const int qr = lane >> 2, qc = lane & 3;
    float* pbase = g_partial + (size_t)ch * (K_EIG * F_DIM);
    #pragma unroll
    for (int mt = 0; mt < 2; mt++) {
        int m = wm * 32 + mt * 16 + qr;
        #pragma unroll
        for (int nt = 0; nt < 4; nt++) {
            int f  = wf * 32 + nt * 8 + 2 * qc;
            int kq = kt * 128 + m;
            __stwt((float2*)(pbase + (size_t)kq * F_DIM + f),
                   make_float2(acc[mt][nt][0], acc[mt][nt][1]));
            __stwt((float2*)(pbase + (size_t)(kq + 8) * F_DIM + f),
                   make_float2(acc[mt][nt][2], acc[mt][nt][3]));
        }
    }
}

// ---------------------------------------------------------------------------
// Phase 1.5: y = g[k]*sum_ch partial -> bf16 hi/lo planes
// ---------------------------------------------------------------------------
__global__ void phase15_kernel(const float* __restrict__ g) {
    int v = blockIdx.x * blockDim.x + threadIdx.x;
    int idx = v * 4;
    float4 s = make_float4(0.f, 0.f, 0.f, 0.f);
    #pragma unroll 37
    for (int c = 0; c < NC; c++) {
        float4 p = *(const float4*)(g_partial + (size_t)c * (K_EIG * F_DIM) + idx);
        s.x += p.x; s.y += p.y; s.z += p.z; s.w += p.w;
    }
    float gk = __ldg(&g[idx >> 7]);
    s.x *= gk; s.y *= gk; s.z *= gk; s.w *= gk;

    __nv_bfloat16 h[4], l[4];
    float sv[4] = {s.x, s.y, s.z, s.w};
    #pragma unroll
    for (int i = 0; i < 4; i++) {
        h[i] = __float2bfloat16_rn(sv[i]);
        l[i] = __float2bfloat16_rn(sv[i] - __bfloat162float(h[i]));
    }
    *(uint2*)(g_yh + idx) = make_uint2(pack2(h[0], h[1]), pack2(h[2], h[3]));
    *(uint2*)(g_yl + idx) = make_uint2(pack2(l[0], l[1]), pack2(l[2], l[3]));
}

// ---------------------------------------------------------------------------
// Phase 2: out[n][f] = relu( sum_k U[n,k] * y[k,f] )
// 391 CTAs, 512 threads (16 warps), warp tile 32(n) x 32(f).
// ---------------------------------------------------------------------------
__global__ void __launch_bounds__(512)
phase2_kernel(const float* __restrict__ U, float* __restrict__ out) {
    extern __shared__ unsigned short smw[];
    const unsigned sbase = (unsigned)__cvta_generic_to_shared(smw);

    const int nb   = blockIdx.x * 128;
    const int tid  = threadIdx.x;
    const int lane = tid & 31;
    const int wid  = tid >> 5;
    const int wm   = wid >> 2;            // 0..3 (n 32-strips)
    const int wf   = wid & 3;             // 0..3 (f 32-strips)

    int urow[2], ucol[2], yrow[2], ycol[2];
    #pragma unroll
    for (int i = 0; i < 2; i++) {
        int e = tid + i * 512;
        urow[i] = e >> 3;
        ucol[i] = (e & 7) << 2;
        yrow[i] = e >> 5;
        ycol[i] = (e & 31) << 2;
    }

    const int lr   = lane & 7;
    const int arow = ((lane >> 3) & 1) * 8 + lr;       // non-trans A
    const int acol = ((lane >> 4) & 1) * 8;
    const int brow = ((lane >> 3) & 1) * 8 + lr;       // trans B
    const int bcol = ((lane >> 4) & 1) * 8;
    unsigned aoffs[2], boffs[2];
    #pragma unroll
    for (int mt = 0; mt < 2; mt++)
        aoffs[mt] = (unsigned)((wm * 32 + mt * 16 + arow) * P2_USTR + acol);
    #pragma unroll
    for (int blk = 0; blk < 2; blk++)
        boffs[blk] = (unsigned)(brow * P2_YSTR + wf * 32 + blk * 16 + bcol);

    float acc[2][4][4];
    #pragma unroll
    for (int a = 0; a < 2; a++)
        #pragma unroll
        for (int b = 0; b < 4; b++)
            #pragma unroll
            for (int c = 0; c < 4; c++) acc[a][b][c] = 0.f;

    float4 rU[2];
    uint2  rYh[2], rYl[2];
    #pragma unroll
    for (int i = 0; i < 2; i++) {
        int n = nb + urow[i];
        rU[i] = (n < N_NODES)
              ? *(const float4*)(U + (size_t)n * K_EIG + ucol[i])
              : make_float4(0.f, 0.f, 0.f, 0.f);
        rYh[i] = *(const uint2*)(g_yh + (size_t)yrow[i] * F_DIM + ycol[i]);
        rYl[i] = *(const uint2*)(g_yl + (size_t)yrow[i] * F_DIM + ycol[i]);
    }

    const int NST2 = K_EIG / 32;
    for (int s = 0; s < NST2; s++) {
        unsigned short* st = smw + (s & 1) * P2_STG;
        #pragma unroll
        for (int i = 0; i < 2; i++) {
            uint2 h, l;
            split4(rU[i], h, l);
            int uoff = urow[i] * P2_USTR + ucol[i];
            *(uint2*)(st + uoff)           = h;
            *(uint2*)(st + P2_USZ + uoff)  = l;
            int yoff = yrow[i] * P2_YSTR + ycol[i];
            *(uint2*)(st + 2 * P2_USZ + yoff)           = rYh[i];
            *(uint2*)(st + 2 * P2_USZ + P2_YSZ + yoff)  = rYl[i];
        }
        __syncthreads();

        if (s + 1 < NST2) {
            int kk = (s + 1) * 32;
            #pragma unroll
            for (int i = 0; i < 2; i++) {
                int n = nb + urow[i];
                rU[i] = (n < N_NODES)
                      ? *(const float4*)(U + (size_t)n * K_EIG + kk + ucol[i])
                      : make_float4(0.f, 0.f, 0.f, 0.f);
                rYh[i] = *(const uint2*)(g_yh + (size_t)(kk + yrow[i]) * F_DIM + ycol[i]);
                rYl[i] = *(const uint2*)(g_yl + (size_t)(kk + yrow[i]) * F_DIM + ycol[i]);
            }
        }

        const unsigned stg = (s & 1) * P2_STG;
        #pragma unroll
        for (int c = 0; c < 2; c++) {
            unsigned ah[2][4], al[2][4], bh[4][2], bl[4][2];
            #pragma unroll
            for (int mt = 0; mt < 2; mt++) {
                LDSM_N(ah[mt], sbase + (stg + aoffs[mt] + c * 16) * 2);
                LDSM_N(al[mt], sbase + (stg + P2_USZ + aoffs[mt] + c * 16) * 2);
            }
            #pragma unroll
            for (int blk = 0; blk < 2; blk++) {
                unsigned t[4];
                LDSM_T(t, sbase + (stg + 2 * P2_USZ + c * 16 * P2_YSTR + boffs[blk]) * 2);
                bh[blk * 2][0] = t[0]; bh[blk * 2][1] = t[1];
                bh[blk * 2 + 1][0] = t[2]; bh[blk * 2 + 1][1] = t[3];
                LDSM_T(t, sbase + (stg + 2 * P2_USZ + P2_YSZ + c * 16 * P2_YSTR + boffs[blk]) * 2);
                bl[blk * 2][0] = t[0]; bl[blk * 2][1] = t[1];
                bl[blk * 2 + 1][0] = t[2]; bl[blk * 2 + 1][1] = t[3];
            }
            #pragma unroll
            for (int mt = 0; mt < 2; mt++)
                #pragma unroll
                for (int nt = 0; nt < 4; nt++) {
                    MMA16(acc[mt][nt], al[mt], bh[nt][0], bh[nt][1]);
                    MMA16(acc[mt][nt], ah[mt], bl[nt][0], bl[nt][1]);
                    MMA16(acc[mt][nt], ah[mt], bh[nt][0], bh[nt][1]);
                }
        }
        __syncthreads();
    }

    const int qr = lane >> 2, qc = lane & 3;
    #pragma unroll
    for (int mt = 0; mt < 2; mt++) {
        int n = nb + wm * 32 + mt * 16 + qr;
        #pragma unroll
        for (int nt = 0; nt < 4; nt++) {
            int f = wf * 32 + nt * 8 + 2 * qc;
            if (n < N_NODES) {
                *(float2*)(out + (size_t)n * F_DIM + f) =
                    make_float2(fmaxf(acc[mt][nt][0], 0.f),
                                fmaxf(acc[mt][nt][1], 0.f));
            }
            if (n + 8 < N_NODES) {
                *(float2*)(out + (size_t)(n + 8) * F_DIM + f) =
                    make_float2(fmaxf(acc[mt][nt][2], 0.f),
                                fmaxf(acc[mt][nt][3], 0.f));
            }
        }
    }
}

// ---------------------------------------------------------------------------
extern "C" void kernel_launch(void* const* d_in, const int* in_sizes, int n_in,
                              void* d_out, int out_size) {
    const float* U = nullptr;
    const float* g = nullptr;
    const float* x = nullptr;
    for (int i = 0; i < n_in; i++) {
        if (in_sizes[i] == N_NODES * K_EIG)      U = (const float*)d_in[i];
        else if (in_sizes[i] == K_EIG)           g = (const float*)d_in[i];
        else if (in_sizes[i] == N_NODES * F_DIM) x = (const float*)d_in[i];
    }
    float* out = (float*)d_out;

    cudaFuncSetAttribute(phase1_kernel,
                         cudaFuncAttributeMaxDynamicSharedMemorySize, P1_SMEM);
    cudaFuncSetAttribute(phase2_kernel,
                         cudaFuncAttributeMaxDynamicSharedMemorySize, P2_SMEM);

    phase1_kernel<<<dim3(4, NC), 512, P1_SMEM>>>(U, x);
    phase15_kernel<<<(K_EIG * F_DIM) / 1024, 256>>>(g);
    phase2_kernel<<<(N_NODES + 127) / 128, 512, P2_SMEM>>>(U, out);
}

// round 11
// speedup vs baseline: 3.1639x; 1.2951x over previous
#include <cuda_runtime.h>
#include <cuda_fp16.h>
#include <cstdint>
#include <cstddef>

#define N_NODES 50000
#define K_EIG   512
#define F_DIM   128
#define CH      1376      // 43 stages of 32 rows
#define NC      37        // 4 x 37 = 148 CTAs = one wave
#define NST1    43

// phase1 smem plane geometry (fp16 element units)
#define P1_STR  136                 // 272B row stride -> ldmatrix conflict-free
#define P1_ASZ  (32 * P1_STR)       // 4352 per 32x128 plane
#define P1_STG  (3 * P1_ASZ)        // UH, UL, XH
#define P1_SMEM (2 * P1_STG * 2)    // 52224 B

// phase2 smem
#define P2_USTR 40
#define P2_USZ  (128 * P2_USTR)     // 5120
#define P2_YSTR 136
#define P2_YSZ  (32 * P2_YSTR)      // 4352
#define P2_STG  (2 * P2_USZ + P2_YSZ)   // 14592
#define P2_SMEM (2 * P2_STG * 2)    // 58368 B

__device__ float  g_partial[(size_t)NC * K_EIG * F_DIM];
__device__ __half g_yh[K_EIG * F_DIM];     // y rounded to fp16, [k][f]

// ---------------------------------------------------------------------------
__device__ __forceinline__ unsigned packh(__half a, __half b) {
    return ((unsigned)__half_as_ushort(b) << 16) | __half_as_ushort(a);
}

// split float pair -> packed fp16 hi-pair + lo-pair (hi+lo good to ~2^-24)
__device__ __forceinline__ void split2h(float a, float b, unsigned &hp, unsigned &lp) {
    __half ha = __float2half_rn(a);
    __half hb = __float2half_rn(b);
    __half la = __float2half_rn(a - __half2float(ha));
    __half lb = __float2half_rn(b - __half2float(hb));
    hp = packh(ha, hb);
    lp = packh(la, lb);
}

__device__ __forceinline__ void split4h(float4 v, uint2 &h, uint2 &l) {
    split2h(v.x, v.y, h.x, l.x);
    split2h(v.z, v.w, h.y, l.y);
}

// round float4 -> 4 packed fp16 (no split)
__device__ __forceinline__ uint2 round4h(float4 v) {
    return make_uint2(packh(__float2half_rn(v.x), __float2half_rn(v.y)),
                      packh(__float2half_rn(v.z), __float2half_rn(v.w)));
}

#define LDSM_T(R, addr) \
    asm volatile("ldmatrix.sync.aligned.m8n8.x4.trans.shared.b16 {%0,%1,%2,%3}, [%4];" \
                 : "=r"((R)[0]), "=r"((R)[1]), "=r"((R)[2]), "=r"((R)[3]) : "r"(addr))

#define LDSM_N(R, addr) \
    asm volatile("ldmatrix.sync.aligned.m8n8.x4.shared.b16 {%0,%1,%2,%3}, [%4];" \
                 : "=r"((R)[0]), "=r"((R)[1]), "=r"((R)[2]), "=r"((R)[3]) : "r"(addr))

#define MMA16(C, A, B0, B1) \
    asm volatile("mma.sync.aligned.m16n8k16.row.col.f32.f16.f16.f32 " \
                 "{%0,%1,%2,%3},{%4,%5,%6,%7},{%8,%9},{%0,%1,%2,%3};" \
                 : "+f"((C)[0]), "+f"((C)[1]), "+f"((C)[2]), "+f"((C)[3]) \
                 : "r"((A)[0]), "r"((A)[1]), "r"((A)[2]), "r"((A)[3]), \
                   "r"(B0), "r"(B1))

// ---------------------------------------------------------------------------
// Phase 1: partial[ch][k][f] = sum_{n in chunk} U[n,k] * x[n,f]
// Grid (4,37)=148 CTAs, 256 thr. A=U split fp16 hi/lo; B=x rounded fp16.
// ---------------------------------------------------------------------------
__global__ void __launch_bounds__(256)
phase1_kernel(const float* __restrict__ U, const float* __restrict__ x) {
    extern __shared__ unsigned short smw[];
    const unsigned sbase = (unsigned)__cvta_generic_to_shared(smw);

    const int kt   = blockIdx.x;
    const int ch   = blockIdx.y;
    const int tid  = threadIdx.x;
    const int lane = tid & 31;
    const int wid  = tid >> 5;
    const int wm   = wid >> 2;
    const int wf   = wid & 3;
    const int n0   = ch * CH;

    int lrow[4], lcol[4];
    #pragma unroll
    for (int i = 0; i < 4; i++) {
        int e = tid + i * 256;
        lrow[i] = e >> 5;
        lcol[i] = (e & 31) << 2;
    }

    const int lr   = lane & 7;
    const int arow = ((lane >> 4) & 1) * 8 + lr;
    const int acol = ((lane >> 3) & 1) * 8;
    const int brow = ((lane >> 3) & 1) * 8 + lr;
    const int bcol = ((lane >> 4) & 1) * 8;
    unsigned aoffs[4], boffs[2];
    #pragma unroll
    for (int mt = 0; mt < 4; mt++)
        aoffs[mt] = arow * P1_STR + wm * 64 + mt * 16 + acol;
    #pragma unroll
    for (int blk = 0; blk < 2; blk++)
        boffs[blk] = brow * P1_STR + wf * 32 + blk * 16 + bcol;

    float acc[4][4][4];
    #pragma unroll
    for (int a = 0; a < 4; a++)
        #pragma unroll
        for (int b = 0; b < 4; b++)
            #pragma unroll
            for (int c = 0; c < 4; c++) acc[a][b][c] = 0.f;

    float4 rU[4], rX[4];
    #pragma unroll
    for (int i = 0; i < 4; i++) {
        int n = n0 + lrow[i];
        if (n < N_NODES) {
            rU[i] = *(const float4*)(U + (size_t)n * K_EIG + kt * 128 + lcol[i]);
            rX[i] = *(const float4*)(x + (size_t)n * F_DIM + lcol[i]);
        } else {
            rU[i] = make_float4(0.f, 0.f, 0.f, 0.f);
            rX[i] = rU[i];
        }
    }

    for (int s = 0; s < NST1; s++) {
        unsigned short* st = smw + (s & 1) * P1_STG;
        #pragma unroll
        for (int i = 0; i < 4; i++) {
            uint2 h, l;
            int off = lrow[i] * P1_STR + lcol[i];
            split4h(rU[i], h, l);
            *(uint2*)(st + off)              = h;     // UH
            *(uint2*)(st + P1_ASZ + off)     = l;     // UL
            *(uint2*)(st + 2 * P1_ASZ + off) = round4h(rX[i]);   // XH
        }
        __syncthreads();

        if (s + 1 < NST1) {
            #pragma unroll
            for (int i = 0; i < 4; i++) {
                int n = n0 + (s + 1) * 32 + lrow[i];
                if (n < N_NODES) {
                    rU[i] = *(const float4*)(U + (size_t)n * K_EIG + kt * 128 + lcol[i]);
                    rX[i] = *(const float4*)(x + (size_t)n * F_DIM + lcol[i]);
                } else {
                    rU[i] = make_float4(0.f, 0.f, 0.f, 0.f);
                    rX[i] = rU[i];
                }
            }
        }

        const unsigned stg = (s & 1) * P1_STG;
        #pragma unroll
        for (int c = 0; c < 2; c++) {
            const unsigned nco = stg + c * 16 * P1_STR;
            unsigned ah[4][4], al[4][4], bh[4][2];
            #pragma unroll
            for (int mt = 0; mt < 4; mt++) {
                LDSM_T(ah[mt], sbase + (nco + aoffs[mt]) * 2);
                LDSM_T(al[mt], sbase + (nco + P1_ASZ + aoffs[mt]) * 2);
            }
            #pragma unroll
            for (int blk = 0; blk < 2; blk++) {
                unsigned t[4];
                LDSM_T(t, sbase + (nco + 2 * P1_ASZ + boffs[blk]) * 2);
                bh[blk * 2][0] = t[0]; bh[blk * 2][1] = t[1];
                bh[blk * 2 + 1][0] = t[2]; bh[blk * 2 + 1][1] = t[3];
            }
            #pragma unroll
            for (int mt = 0; mt < 4; mt++)
                #pragma unroll
                for (int nt = 0; nt < 4; nt++) {
                    MMA16(acc[mt][nt], al[mt], bh[nt][0], bh[nt][1]);
                    MMA16(acc[mt][nt], ah[mt], bh[nt][0], bh[nt][1]);
                }
        }
        __syncthreads();
    }

    const int qr = lane >> 2, qc = lane & 3;
    float* pbase = g_partial + (size_t)ch * (K_EIG * F_DIM);
    #pragma unroll
    for (int mt = 0; mt < 4; mt++) {
        int m = wm * 64 + mt * 16 + qr;
        #pragma unroll
        for (int nt = 0; nt < 4; nt++) {
            int f  = wf * 32 + nt * 8 + 2 * qc;
            int kq = kt * 128 + m;
            __stwt((float2*)(pbase + (size_t)kq * F_DIM + f),
                   make_float2(acc[mt][nt][0], acc[mt][nt][1]));
            __stwt((float2*)(pbase + (size_t)(kq + 8) * F_DIM + f),
                   make_float2(acc[mt][nt][2], acc[mt][nt][3]));
        }
    }
}

// ---------------------------------------------------------------------------
// Phase 1.5: y = g[k]*sum_ch partial -> fp16 plane [k][f]
// ---------------------------------------------------------------------------
__global__ void phase15_kernel(const float* __restrict__ g) {
    int v = blockIdx.x * blockDim.x + threadIdx.x;
    int idx = v * 4;
    float4 s = make_float4(0.f, 0.f, 0.f, 0.f);
    #pragma unroll 37
    for (int c = 0; c < NC; c++) {
        float4 p = *(const float4*)(g_partial + (size_t)c * (K_EIG * F_DIM) + idx);
        s.x += p.x; s.y += p.y; s.z += p.z; s.w += p.w;
    }
    float gk = __ldg(&g[idx >> 7]);
    s.x *= gk; s.y *= gk; s.z *= gk; s.w *= gk;
    *(uint2*)(g_yh + idx) = round4h(s);
}

// ---------------------------------------------------------------------------
// Phase 2: out[n][f] = relu( sum_k U[n,k] * y[k,f] )
// 391 CTAs, 256 thr. A=U split fp16 hi/lo (non-trans); B=y fp16 (trans).
// ---------------------------------------------------------------------------
__global__ void __launch_bounds__(256)
phase2_kernel(const float* __restrict__ U, float* __restrict__ out) {
    extern __shared__ unsigned short smw[];
    const unsigned sbase = (unsigned)__cvta_generic_to_shared(smw);

    const int nb   = blockIdx.x * 128;
    const int tid  = threadIdx.x;
    const int lane = tid & 31;
    const int wid  = tid >> 5;
    const int wm   = wid >> 2;
    const int wf   = wid & 3;

    int urow[4], ucol[4], yrow[4], ycol[4];
    #pragma unroll
    for (int i = 0; i < 4; i++) {
        int e = tid + i * 256;
        urow[i] = e >> 3;
        ucol[i] = (e & 7) << 2;
        yrow[i] = e >> 5;
        ycol[i] = (e & 31) << 2;
    }

    const int lr   = lane & 7;
    const int arow = ((lane >> 3) & 1) * 8 + lr;       // non-trans A
    const int acol = ((lane >> 4) & 1) * 8;
    const int brow = ((lane >> 3) & 1) * 8 + lr;       // trans B
    const int bcol = ((lane >> 4) & 1) * 8;
    unsigned aoffs[4], boffs[2];
    #pragma unroll
    for (int mt = 0; mt < 4; mt++)
        aoffs[mt] = (unsigned)((wm * 64 + mt * 16 + arow) * P2_USTR + acol);
    #pragma unroll
    for (int blk = 0; blk < 2; blk++)
        boffs[blk] = (unsigned)(brow * P2_YSTR + wf * 32 + blk * 16 + bcol);

    float acc[4][4][4];
    #pragma unroll
    for (int a = 0; a < 4; a++)
        #pragma unroll
        for (int b = 0; b < 4; b++)
            #pragma unroll
            for (int c = 0; c < 4; c++) acc[a][b][c] = 0.f;

    float4 rU[4];
    uint2  rYh[4];
    #pragma unroll
    for (int i = 0; i < 4; i++) {
        int n = nb + urow[i];
        rU[i] = (n < N_NODES)
              ? *(const float4*)(U + (size_t)n * K_EIG + ucol[i])
              : make_float4(0.f, 0.f, 0.f, 0.f);
        rYh[i] = *(const uint2*)(g_yh + (size_t)yrow[i] * F_DIM + ycol[i]);
    }

    const int NST2 = K_EIG / 32;
    for (int s = 0; s < NST2; s++) {
        unsigned short* st = smw + (s & 1) * P2_STG;
        #pragma unroll
        for (int i = 0; i < 4; i++) {
            uint2 h, l;
            split4h(rU[i], h, l);
            int uoff = urow[i] * P2_USTR + ucol[i];
            *(uint2*)(st + uoff)           = h;                    // UH
            *(uint2*)(st + P2_USZ + uoff)  = l;                    // UL
            int yoff = yrow[i] * P2_YSTR + ycol[i];
            *(uint2*)(st + 2 * P2_USZ + yoff) = rYh[i];            // YH
        }
        __syncthreads();

        if (s + 1 < NST2) {
            int kk = (s + 1) * 32;
            #pragma unroll
            for (int i = 0; i < 4; i++) {
                int n = nb + urow[i];
                rU[i] = (n < N_NODES)
                      ? *(const float4*)(U + (size_t)n * K_EIG + kk + ucol[i])
                      : make_float4(0.f, 0.f, 0.f, 0.f);
                rYh[i] = *(const uint2*)(g_yh + (size_t)(kk + yrow[i]) * F_DIM + ycol[i]);
            }
        }

        const unsigned stg = (s & 1) * P2_STG;
        #pragma unroll
        for (int c = 0; c < 2; c++) {
            unsigned ah[4][4], al[4][4], bh[4][2];
            #pragma unroll
            for (int mt = 0; mt < 4; mt++) {
                LDSM_N(ah[mt], sbase + (stg + aoffs[mt] + c * 16) * 2);
                LDSM_N(al[mt], sbase + (stg + P2_USZ + aoffs[mt] + c * 16) * 2);
            }
            #pragma unroll
            for (int blk = 0; blk < 2; blk++) {
                unsigned t[4];
                LDSM_T(t, sbase + (stg + 2 * P2_USZ + c * 16 * P2_YSTR + boffs[blk]) * 2);
                bh[blk * 2][0] = t[0]; bh[blk * 2][1] = t[1];
                bh[blk * 2 + 1][0] = t[2]; bh[blk * 2 + 1][1] = t[3];
            }
            #pragma unroll
            for (int mt = 0; mt < 4; mt++)
                #pragma unroll
                for (int nt = 0; nt < 4; nt++) {
                    MMA16(acc[mt][nt], al[mt], bh[nt][0], bh[nt][1]);
                    MMA16(acc[mt][nt], ah[mt], bh[nt][0], bh[nt][1]);
                }
        }
        __syncthreads();
    }

    const int qr = lane >> 2, qc = lane & 3;
    #pragma unroll
    for (int mt = 0; mt < 4; mt++) {
        int n = nb + wm * 64 + mt * 16 + qr;
        #pragma unroll
        for (int nt = 0; nt < 4; nt++) {
            int f = wf * 32 + nt * 8 + 2 * qc;
            if (n < N_NODES) {
                *(float2*)(out + (size_t)n * F_DIM + f) =
                    make_float2(fmaxf(acc[mt][nt][0], 0.f),
                                fmaxf(acc[mt][nt][1], 0.f));
            }
            if (n + 8 < N_NODES) {
                *(float2*)(out + (size_t)(n + 8) * F_DIM + f) =
                    make_float2(fmaxf(acc[mt][nt][2], 0.f),
                                fmaxf(acc[mt][nt][3], 0.f));
            }
        }
    }
}

// ---------------------------------------------------------------------------
extern "C" void kernel_launch(void* const* d_in, const int* in_sizes, int n_in,
                              void* d_out, int out_size) {
    const float* U = nullptr;
    const float* g = nullptr;
    const float* x = nullptr;
    for (int i = 0; i < n_in; i++) {
        if (in_sizes[i] == N_NODES * K_EIG)      U = (const float*)d_in[i];
        else if (in_sizes[i] == K_EIG)           g = (const float*)d_in[i];
        else if (in_sizes[i] == N_NODES * F_DIM) x = (const float*)d_in[i];
    }
    float* out = (float*)d_out;

    cudaFuncSetAttribute(phase1_kernel,
                         cudaFuncAttributeMaxDynamicSharedMemorySize, P1_SMEM);
    cudaFuncSetAttribute(phase2_kernel,
                         cudaFuncAttributeMaxDynamicSharedMemorySize, P2_SMEM);

    phase1_kernel<<<dim3(4, NC), 256, P1_SMEM>>>(U, x);
    phase15_kernel<<<(K_EIG * F_DIM) / 1024, 256>>>(g);
    phase2_kernel<<<(N_NODES + 127) / 128, 256, P2_SMEM>>>(U, out);
}